// round 7
// baseline (speedup 1.0000x reference)
#include <cuda_runtime.h>
#include <cstdint>

// Shapes (fixed by setup_inputs):
//   k_cache: (B=4, H=8, D=128, 128, 64) f32 -> (BH=32, D=128, SFULL=8192)
//   v_cache: (B=4, H=8, 128, 64, D=128) f32 -> (BH=32, SFULL=8192, D=128)
//   S = 6144 (derived from out_size)
// out = stack([transpose_k(:, :, :S), v(:, :S, :)]) -> (2, BH, S, D)

#define BH_    32
#define D_     128
#define SFULL_ 8192

// sigma(s): 5-bit rotate; XOR swizzle conflict-free for scalar STS and LDS.128.
__device__ __forceinline__ int sigma5(int s) {
    return ((s & 3) << 3) | (s >> 2);
}

// Grid = groups of 3 blocks: r=0,1 -> K-transpose tiles (16 KB each),
// r=2 -> V copy chunk (32 KB, two 4-deep load batches).
__global__ __launch_bounds__(256, 8) void fused_kv_kernel(
    const float*  __restrict__ kin,
    const float4* __restrict__ vin,
    float4*       __restrict__ outk,
    float4*       __restrict__ outv,
    int S, int ktilesPerBh, int vtilesPerBh)
{
    const int b = blockIdx.x;
    const int t = threadIdx.x;
    const int g = b / 3;
    const int r = b - 3 * g;

    if (r == 2) {
        // ---------------- V copy: contiguous 32 KB chunk --------------------
        const int id = g;
        const int bh = id / vtilesPerBh;
        const int jj = id - bh * vtilesPerBh;
        const float4* src = vin  + (size_t)bh * (SFULL_ * (D_ / 4)) + (size_t)jj * 2048;
        float4*       dst = outv + (size_t)bh * ((size_t)S * (D_ / 4)) + (size_t)jj * 2048;

        // Batch 1: 4-deep MLP.
        float4 v0 = __ldcs(src + t);
        float4 v1 = __ldcs(src + t + 256);
        float4 v2 = __ldcs(src + t + 512);
        float4 v3 = __ldcs(src + t + 768);
        __stcs(dst + t,       v0);
        __stcs(dst + t + 256, v1);
        __stcs(dst + t + 512, v2);
        __stcs(dst + t + 768, v3);
        // Batch 2: issued immediately, no block-boundary drain.
        float4 v4 = __ldcs(src + t + 1024);
        float4 v5 = __ldcs(src + t + 1280);
        float4 v6 = __ldcs(src + t + 1536);
        float4 v7 = __ldcs(src + t + 1792);
        __stcs(dst + t + 1024, v4);
        __stcs(dst + t + 1280, v5);
        __stcs(dst + t + 1536, v6);
        __stcs(dst + t + 1792, v7);
    } else {
        // -------------- K transpose: (D=128, s=32) -> (s=32, D=128) ---------
        // Flat 32(s) x 32(q) float4 tile, cell (s,q) at p = q ^ sigma(s).
        __shared__ float tile[32 * 128];   // 16 KB

        const int id = 2 * g + r;
        const int bh = id / ktilesPerBh;
        const int jj = id - bh * ktilesPerBh;

        const int s0 = jj * 32;
        const float* src = kin + (size_t)bh * D_ * SFULL_ + s0;
        float4*      dst = outk + ((size_t)bh * (size_t)S * D_
                                   + (size_t)s0 * D_) / 4;

        // Load: 1024 float4 (4 consecutive s at fixed d), 4-deep MLP.
        float4 rr4[4];
#pragma unroll
        for (int i = 0; i < 4; ++i) {
            const int idx = t + i * 256;
            const int d = idx >> 3;       // 0..127
            const int f = idx & 7;        // float4 index along s
            rr4[i] = __ldcs((const float4*)(src + (size_t)d * SFULL_ + 4 * f));
        }

        // Scatter to swizzled smem (all 32 banks hit once per STS pass).
#pragma unroll
        for (int i = 0; i < 4; ++i) {
            const int idx = t + i * 256;
            const int d = idx >> 3;
            const int f = idx & 7;
            const int q = d >> 2;
            const int rm = d & 3;
#pragma unroll
            for (int k = 0; k < 4; ++k) {
                const int s = 4 * f + k;
                const int p = q ^ sigma5(s);
                const float comp = (k == 0) ? rr4[i].x : (k == 1) ? rr4[i].y
                                 : (k == 2) ? rr4[i].z : rr4[i].w;
                tile[s * 128 + p * 4 + rm] = comp;
            }
        }
        __syncthreads();

        // Drain: LDS.128 conflict-free, STG.128 512 B contiguous per warp,
        // block writes a fully contiguous 16 KB output region.
        const float4* tile4 = (const float4*)tile;
#pragma unroll
        for (int i = 0; i < 4; ++i) {
            const int e = t + i * 256;    // 0..1023
            const int s = e >> 5;         // 0..31
            const int q = e & 31;         // 0..31
            __stcs(dst + e, tile4[s * 32 + (q ^ sigma5(s))]);
        }
    }
}

extern "C" void kernel_launch(void* const* d_in, const int* in_sizes, int n_in,
                              void* d_out, int out_size) {
    const float* k_cache = (const float*)d_in[0];
    const float* v_cache = (const float*)d_in[1];
    // seq_len fully determined by out_size: out = 2 * BH * S * D elems.
    const int S = out_size / (2 * BH_ * D_);        // 6144
    const int ktilesPerBh = S / 32;                 // 192 (16 KB K tiles)
    const int vtilesPerBh = S / 64;                 // 96  (32 KB V chunks)

    float4* out_k = (float4*)d_out;                                 // (BH,S,D)
    float4* out_v = (float4*)((float*)d_out + (size_t)BH_ * S * D_);

    dim3 block(256, 1, 1);
    // 3 blocks per group: 2 K tiles + 1 V chunk. Groups = BH * 96 = 3072.
    dim3 grid((unsigned)(3 * BH_ * vtilesPerBh), 1, 1);             // 9216
    fused_kv_kernel<<<grid, block>>>(k_cache, (const float4*)v_cache,
                                     out_k, out_v, S, ktilesPerBh, vtilesPerBh);
}

// round 8
// speedup vs baseline: 1.0050x; 1.0050x over previous
#include <cuda_runtime.h>
#include <cstdint>

// Shapes (fixed by setup_inputs):
//   k_cache: (B=4, H=8, D=128, 128, 64) f32 -> (BH=32, D=128, SFULL=8192)
//   v_cache: (B=4, H=8, 128, 64, D=128) f32 -> (BH=32, SFULL=8192, D=128)
//   S = 6144 (derived from out_size)
// out = stack([transpose_k(:, :, :S), v(:, :S, :)]) -> (2, BH, S, D)

#define BH_    32
#define D_     128
#define SFULL_ 8192
#define NSLOT_ 1184   // 148 SMs x 8 resident CTAs

// R2 body (proven best: 78% DRAM), wave-balanced grid:
//   unit id even -> K-transpose tile (d=128 x s=32), 16 KB contiguous output
//   unit id odd  -> V copy chunk (1024 float4, 16 KB), 4-deep batched MLP
// Grid = 10 exact waves; first `extra` blocks take a second unit so the
// final wave is full instead of 38% occupied.
__global__ __launch_bounds__(256, 8) void fused_kv_kernel(
    const float*  __restrict__ kin,
    const float4* __restrict__ vin,
    float*        __restrict__ outk,
    float4*       __restrict__ outv,
    int S, int tilesPerBh, int nGrid, int extra)
{
    __shared__ float tile[32][129];

    const int t = threadIdx.x;
    int unit = blockIdx.x;
    const int nIter = (blockIdx.x < extra) ? 2 : 1;

    for (int it = 0; it < nIter; ++it) {
        const int id = unit >> 1;
        const int bh = id / tilesPerBh;
        const int jj = id - bh * tilesPerBh;

        if (unit & 1) {
            // ---------------- V copy: contiguous 16 KB chunk ----------------
            const float4* src = vin  + (size_t)bh * (SFULL_ * (D_ / 4)) + (size_t)jj * 1024;
            float4*       dst = outv + (size_t)bh * ((size_t)S * (D_ / 4)) + (size_t)jj * 1024;

            float4 v0 = src[t];
            float4 v1 = src[t + 256];
            float4 v2 = src[t + 512];
            float4 v3 = src[t + 768];
            dst[t]       = v0;
            dst[t + 256] = v1;
            dst[t + 512] = v2;
            dst[t + 768] = v3;
        } else {
            // ------------ K transpose: (D=128, s=32) -> (s=32, D=128) -------
            // tile[s][d], row stride 129:
            //   STS bank = (4f+k+d) mod 32 -> all 32 banks once per warp
            //   LDS bank = (s+d)    mod 32 -> conflict-free
            if (it != 0) __syncthreads();   // prior drain done before refill

            const int s0 = jj * 32;
            const float* src = kin  + (size_t)bh * D_ * SFULL_ + s0;
            float*       dst = outk + (size_t)bh * (size_t)S * D_ + (size_t)s0 * D_;

            // Load: 1024 float4, all 4 LDGs batched (4-deep MLP); each 8-lane
            // group reads a contiguous 128 B of one d-row.
            float4 r[4];
#pragma unroll
            for (int i = 0; i < 4; ++i) {
                const int idx = t + i * 256;
                const int d = idx >> 3;       // 0..127
                const int f = idx & 7;        // float4 index along s
                r[i] = *(const float4*)(src + (size_t)d * SFULL_ + 4 * f);
            }
#pragma unroll
            for (int i = 0; i < 4; ++i) {
                const int idx = t + i * 256;
                const int d = idx >> 3;
                const int f = idx & 7;
                tile[4 * f + 0][d] = r[i].x;
                tile[4 * f + 1][d] = r[i].y;
                tile[4 * f + 2][d] = r[i].z;
                tile[4 * f + 3][d] = r[i].w;
            }
            __syncthreads();

            // Drain: each warp writes a contiguous 128 B segment; block
            // writes a fully contiguous 16 KB output region.
#pragma unroll
            for (int i = 0; i < 16; ++i) {
                const int e = t + i * 256;
                const int s = e >> 7;         // 0..31
                const int d = e & 127;        // 0..127
                dst[(size_t)s * D_ + d] = tile[s][d];
            }
        }
        unit += nGrid;   // second unit has same parity (nGrid even)
    }
}

extern "C" void kernel_launch(void* const* d_in, const int* in_sizes, int n_in,
                              void* d_out, int out_size) {
    const float* k_cache = (const float*)d_in[0];
    const float* v_cache = (const float*)d_in[1];
    // seq_len fully determined by out_size: out = 2 * BH * S * D elems.
    const int S = out_size / (2 * BH_ * D_);        // 6144
    const int tilesPerBh = S / 32;                  // 192
    const int totalUnits = 2 * BH_ * tilesPerBh;    // 12288

    // Exact-wave grid: largest multiple of NSLOT_ <= totalUnits (even).
    int nGrid = (totalUnits / NSLOT_) * NSLOT_;     // 11840
    if (nGrid == 0) nGrid = totalUnits;
    const int extra = totalUnits - nGrid;           // 448 double-duty blocks

    float*  out_k = (float*)d_out;                                  // (BH,S,D)
    float4* out_v = (float4*)((float*)d_out + (size_t)BH_ * S * D_);

    dim3 block(256, 1, 1);
    dim3 grid((unsigned)nGrid, 1, 1);
    fused_kv_kernel<<<grid, block>>>(k_cache, (const float4*)v_cache,
                                     out_k, out_v, S, tilesPerBh, nGrid, extra);
}